// round 5
// baseline (speedup 1.0000x reference)
#include <cuda_runtime.h>
#include <cstdint>

#define NB 4
#define CH 256
#define NN 4096
#define QSCALE 0.0625f   // 1/sqrt(256)

// ---------------- scratch (static __device__, no allocation) ----------------
__device__ float g_k[NB * CH * NN];        // 16 MB
__device__ float g_v[NB * CH * NN];        // 16 MB
__device__ float g_invD[NB * NN];
__device__ float g_Wm[NB * 5 * NN];        // band weights: [b][d][n], d: m = n + d - 2
__device__ float g_gc[NB * CH];            // rank-1 term per (b, c)

// ---------------- packed f32x2 helpers (Blackwell FFMA2) ----------------
__device__ __forceinline__ void ffma2(unsigned long long& d,
                                      unsigned long long a,
                                      unsigned long long b) {
    asm("fma.rn.f32x2 %0, %1, %2, %0;" : "+l"(d) : "l"(a), "l"(b));
}
__device__ __forceinline__ unsigned long long pack2(float x, float y) {
    unsigned long long r;
    asm("mov.b64 %0, {%1, %2};" : "=l"(r) : "f"(x), "f"(y));
    return r;
}

// ================= Kernel 1: fused k/v GEMM =================
// k[b,r,n] = sum_c Wk[r,c] * inp[b,c,n];  v likewise with Wv.
// Tiles: BM=64 (r) x BN=64 (n) x BK=16 (c), both outputs share the X tile.
#define BM 64
#define BN 64
#define BK 16

__global__ __launch_bounds__(256) void kv_gemm_kernel(const float* __restrict__ inp,
                                                      const float* __restrict__ Wk,
                                                      const float* __restrict__ Wv) {
    const int b   = blockIdx.z;
    const int rm0 = blockIdx.y * BM;
    const int n0  = blockIdx.x * BN;
    const float* X = inp + (size_t)b * CH * NN;

    // W fragments stored as duplicated f32 pairs so FFMA2 broadcasts for free.
    __shared__ __align__(16) unsigned long long sWk[BK][BM + 2];
    __shared__ __align__(16) unsigned long long sWv[BK][BM + 2];
    __shared__ __align__(16) float sX[BK][BN];

    const int tid = threadIdx.x;
    const int tx = tid & 15;   // n-tile position (4 cols each)
    const int ty = tid >> 4;   // r-tile position (4 rows each)

    unsigned long long ack[4][2];
    unsigned long long acv[4][2];
#pragma unroll
    for (int i = 0; i < 4; i++) {
        ack[i][0] = 0ull; ack[i][1] = 0ull;
        acv[i][0] = 0ull; acv[i][1] = 0ull;
    }

    const int wc = tid & 15;   // W loader: col within BK
    const int wr = tid >> 4;   // W loader: row base (step 16)
    const int xn = tid & 63;   // X loader: n within BN
    const int xc = tid >> 6;   // X loader: c base (step 4)

    for (int t = 0; t < CH; t += BK) {
#pragma unroll
        for (int i = 0; i < 4; i++) {
            int r = wr + i * 16;
            float a  = Wk[(rm0 + r) * CH + t + wc];
            float bb = Wv[(rm0 + r) * CH + t + wc];
            sWk[wc][r] = pack2(a, a);
            sWv[wc][r] = pack2(bb, bb);
        }
#pragma unroll
        for (int i = 0; i < 4; i++) {
            int c = xc + i * 4;
            sX[c][xn] = X[(size_t)(t + c) * NN + n0 + xn];
        }
        __syncthreads();
#pragma unroll
        for (int kk = 0; kk < BK; kk++) {
            const ulonglong2 xp = *reinterpret_cast<const ulonglong2*>(&sX[kk][tx * 4]);
            const ulonglong2 a0 = *reinterpret_cast<const ulonglong2*>(&sWk[kk][ty * 4]);
            const ulonglong2 a1 = *reinterpret_cast<const ulonglong2*>(&sWk[kk][ty * 4 + 2]);
            const ulonglong2 b0 = *reinterpret_cast<const ulonglong2*>(&sWv[kk][ty * 4]);
            const ulonglong2 b1 = *reinterpret_cast<const ulonglong2*>(&sWv[kk][ty * 4 + 2]);
            ffma2(ack[0][0], a0.x, xp.x); ffma2(ack[0][1], a0.x, xp.y);
            ffma2(ack[1][0], a0.y, xp.x); ffma2(ack[1][1], a0.y, xp.y);
            ffma2(ack[2][0], a1.x, xp.x); ffma2(ack[2][1], a1.x, xp.y);
            ffma2(ack[3][0], a1.y, xp.x); ffma2(ack[3][1], a1.y, xp.y);
            ffma2(acv[0][0], b0.x, xp.x); ffma2(acv[0][1], b0.x, xp.y);
            ffma2(acv[1][0], b0.y, xp.x); ffma2(acv[1][1], b0.y, xp.y);
            ffma2(acv[2][0], b1.x, xp.x); ffma2(acv[2][1], b1.x, xp.y);
            ffma2(acv[3][0], b1.y, xp.x); ffma2(acv[3][1], b1.y, xp.y);
        }
        __syncthreads();
    }
#pragma unroll
    for (int i = 0; i < 4; i++) {
        size_t row = ((size_t)b * CH + rm0 + ty * 4 + i) * NN + n0 + tx * 4;
        ulonglong2 ks; ks.x = ack[i][0]; ks.y = ack[i][1];
        *reinterpret_cast<ulonglong2*>(&g_k[row]) = ks;
        ulonglong2 vs; vs.x = acv[i][0]; vs.y = acv[i][1];
        *reinterpret_cast<ulonglong2*>(&g_v[row]) = vs;
    }
}

// ================= Kernel 2: band scores -> softmax weights =================
// For each (b, n): s[d] = sum_r q[r,n] * k[r, n+d-2], d = 0..4 (valid m only).
// D(n) = sum_valid exp(s[d]) + (N - n_valid);  g_Wm[b][d][n] = (exp(s[d])-1)/D.
__global__ __launch_bounds__(256) void score_kernel(const float* __restrict__ hidden) {
    const int b  = blockIdx.y;
    const int n0 = blockIdx.x * 64;
    const int tid = threadIdx.x;
    const int tx = tid & 63;   // n within tile
    const int ty = tid >> 6;   // r-split group (0..3)
    const float* q  = hidden + (size_t)b * CH * NN;
    const float* kb = g_k    + (size_t)b * CH * NN;

    __shared__ float sk[8][72];        // 8 k-rows, 64 n + 4 halo
    __shared__ float red[4][5][64];

    float acc[5] = {0.f, 0.f, 0.f, 0.f, 0.f};

    for (int rb = 0; rb < CH; rb += 8) {
        __syncthreads();
        for (int i = tid; i < 8 * 68; i += 256) {
            int rr = i / 68;
            int j  = i - rr * 68;
            int ns = n0 - 2 + j;
            sk[rr][j] = ((unsigned)ns < (unsigned)NN)
                            ? kb[(size_t)(rb + rr) * NN + ns] : 0.f;
        }
        __syncthreads();
#pragma unroll
        for (int h = 0; h < 2; h++) {
            int rr = ty + h * 4;
            float qv = q[(size_t)(rb + rr) * NN + n0 + tx] * QSCALE;
#pragma unroll
            for (int d = 0; d < 5; d++) acc[d] += qv * sk[rr][tx + d];
        }
    }
    __syncthreads();
#pragma unroll
    for (int d = 0; d < 5; d++) red[ty][d][tx] = acc[d];
    __syncthreads();

    if (ty == 0) {
        int n = n0 + tx;
        float D = 0.f;
        float w[5];
        int nv = 0;
#pragma unroll
        for (int d = 0; d < 5; d++) {
            float s = red[0][d][tx] + red[1][d][tx] + red[2][d][tx] + red[3][d][tx];
            int m = n + d - 2;
            if ((unsigned)m < (unsigned)NN) {
                float e = expf(s);
                D += e;
                w[d] = e - 1.f;
                nv++;
            } else {
                w[d] = 0.f;
            }
        }
        D += (float)(NN - nv);   // off-band entries contribute exp(0)=1 each
        float inv = 1.f / D;
        g_invD[b * NN + n] = inv;
#pragma unroll
        for (int d = 0; d < 5; d++)
            g_Wm[((size_t)b * 5 + d) * NN + n] = w[d] * inv;
    }
}

// ================= Kernel 3: rank-1 term g[b,c] = sum_n v[b,c,n]/D(n) =======
__global__ __launch_bounds__(256) void gsum_kernel() {
    const int b = blockIdx.y;
    const int c = blockIdx.x;
    const float* v    = g_v + ((size_t)b * CH + c) * NN;
    const float* invD = g_invD + b * NN;
    float s = 0.f;
    for (int n = threadIdx.x; n < NN; n += 256) s += v[n] * invD[n];
    __shared__ float sr[256];
    sr[threadIdx.x] = s;
    __syncthreads();
    for (int k = 128; k > 0; k >>= 1) {
        if (threadIdx.x < k) sr[threadIdx.x] += sr[threadIdx.x + k];
        __syncthreads();
    }
    if (threadIdx.x == 0) g_gc[b * CH + c] = sr[0];
}

// ================= Kernel 4: epilogue =================
// out[b,c,m] = inp[b,c,m] + g[b,c] + sum_{|o|<=2} v[b,c,m+o] * Wm[b][2-o][m+o]
__global__ __launch_bounds__(256) void out_kernel(const float* __restrict__ inp,
                                                  float* __restrict__ out) {
    const int b  = blockIdx.z;
    const int c  = blockIdx.y;
    const int m0 = blockIdx.x * 256;
    const int tid = threadIdx.x;
    const float* v = g_v + ((size_t)b * CH + c) * NN;

    __shared__ float sv[260];
    for (int i = tid; i < 260; i += 256) {
        int ns = m0 - 2 + i;
        sv[i] = ((unsigned)ns < (unsigned)NN) ? v[ns] : 0.f;
    }
    __syncthreads();

    const int m = m0 + tid;
    const size_t idx = ((size_t)b * CH + c) * NN + m;
    float acc = inp[idx] + g_gc[b * CH + c];
#pragma unroll
    for (int o = -2; o <= 2; o++) {
        int n = m + o;
        if ((unsigned)n < (unsigned)NN) {
            acc += sv[tid + 2 + o] * g_Wm[((size_t)b * 5 + (2 - o)) * NN + n];
        }
    }
    out[idx] = acc;
}

// ================= launch =================
extern "C" void kernel_launch(void* const* d_in, const int* in_sizes, int n_in,
                              void* d_out, int out_size) {
    const float* inp    = (const float*)d_in[0];
    const float* hidden = (const float*)d_in[1];
    const float* Wk     = (const float*)d_in[2];
    const float* Wv     = (const float*)d_in[3];
    float* out = (float*)d_out;

    kv_gemm_kernel<<<dim3(NN / BN, CH / BM, NB), 256>>>(inp, Wk, Wv);
    score_kernel<<<dim3(NN / 64, NB), 256>>>(hidden);
    gsum_kernel<<<dim3(CH, NB), 256>>>();
    out_kernel<<<dim3(NN / 256, CH, NB), 256>>>(inp, out);
}

// round 11
// speedup vs baseline: 2.2438x; 2.2438x over previous
#include <cuda_runtime.h>
#include <cuda_bf16.h>
#include <cstdint>

#define NB 4
#define CH 256
#define NN 4096
#define QSCALE 0.0625f   // 1/sqrt(256)

// ---------------- scratch (static __device__, no allocation) ----------------
__device__ float g_k[NB * CH * NN];        // 16 MB
__device__ float g_v[NB * CH * NN];        // 16 MB
__device__ float g_invD[NB * NN];
__device__ float g_Wm[NB * 5 * NN];        // band weights: [b][d][n], d: m = n + d - 2
__device__ float g_gc[NB * CH];            // rank-1 term per (b, c)

// ================= portable PTX helpers (sm_80-level only) =================
__device__ __forceinline__ uint32_t s2u(const void* p) {
    uint32_t a;
    asm("{ .reg .u64 t; cvta.to.shared.u64 t, %1; cvt.u32.u64 %0, t; }"
        : "=r"(a) : "l"(p));
    return a;
}

#define LDSM_X4(R, addr) \
    asm volatile("ldmatrix.sync.aligned.m8n8.x4.shared.b16 {%0,%1,%2,%3}, [%4];" \
        : "=r"((R)[0]), "=r"((R)[1]), "=r"((R)[2]), "=r"((R)[3]) : "r"(addr))

#define LDSM_X4T(R, addr) \
    asm volatile("ldmatrix.sync.aligned.m8n8.x4.trans.shared.b16 {%0,%1,%2,%3}, [%4];" \
        : "=r"((R)[0]), "=r"((R)[1]), "=r"((R)[2]), "=r"((R)[3]) : "r"(addr))

#define MMA16816(D, A, B0, B1) \
    asm volatile("mma.sync.aligned.m16n8k16.row.col.f32.bf16.bf16.f32 " \
        "{%0,%1,%2,%3}, {%4,%5,%6,%7}, {%8,%9}, {%0,%1,%2,%3};" \
        : "+f"((D)[0]), "+f"((D)[1]), "+f"((D)[2]), "+f"((D)[3]) \
        : "r"((A)[0]), "r"((A)[1]), "r"((A)[2]), "r"((A)[3]), "r"(B0), "r"(B1))

// ================= Kernel 1: HMMA bf16 fused k/v GEMM =================
// Per CTA: batch b, 128 n-cols, ALL 256 output rows (m), K = 256.
//   X tile resident in smem: 256 rows (c = K-dim) x 128 n bf16, row pitch 272B.
//   W streamed in K-chunks of 32: 256 rows (m) x 32 k bf16, row pitch 80B, 2 bufs.
// Warp grid 4(m) x 2(n): warp tile 64m x 64n. m16n8k16 HMMA, fp32 accum.
#define XPITCH 272
#define WPITCH 80
#define SM_X   0
#define SM_W0  69632                 // 256*272
#define SM_W1  90112                 // SM_W0 + 256*80
#define SM_TOT 110592                // SM_W1 + 256*80

__global__ __launch_bounds__(256) void kv_mma_kernel(const float* __restrict__ inp,
                                                     const float* __restrict__ Wk,
                                                     const float* __restrict__ Wv) {
    extern __shared__ char smem[];
    const uint32_t sb = s2u(smem);
    const int tid = threadIdx.x;
    const int wid = tid >> 5;
    const int lane = tid & 31;
    const int b = blockIdx.y;
    const int n0 = blockIdx.x * 128;
    const float* X = inp + (size_t)b * CH * NN;

    // ---- load X resident tile: fp32 -> bf16, rows pitch 272B ----
    {
        const int nn4 = (tid & 31) * 4;
#pragma unroll 8
        for (int it = 0; it < 32; it++) {
            int c = (tid >> 5) + it * 8;
            float4 x = *reinterpret_cast<const float4*>(&X[(size_t)c * NN + n0 + nn4]);
            union { __nv_bfloat162 h[2]; uint2 u; } cv;
            cv.h[0] = __floats2bfloat162_rn(x.x, x.y);
            cv.h[1] = __floats2bfloat162_rn(x.z, x.w);
            *reinterpret_cast<uint2*>(smem + SM_X + c * XPITCH + nn4 * 2) = cv.u;
        }
    }

    // warp tile coords + ldmatrix lane addresses
    const int wm = (wid >> 1) * 64;       // m base (4 warps over 256 rows)
    const int wn = (wid & 1) * 64;        // n base (2 warps over 128 cols)
    // A: threads 0-15 -> rows m+(t&15) at k+0 (16B), 16-31 -> same rows at k+16B
    const uint32_t aoff = (uint32_t)((wm + (lane & 15)) * WPITCH + ((lane & 16) ? 16 : 0));
    // B (trans): threads 0-15 -> k-rows (t&15), col block wn (+8 for upper half pair)
    const uint32_t addrB0 = sb + SM_X + (uint32_t)((lane & 15) * XPITCH +
                                                   (wn + ((lane & 16) ? 8 : 0)) * 2);

    const int wr = tid >> 3;              // W loader: row base (stride 32)
    const int wc4 = (tid & 7) * 4;        // W loader: 4-col group

#pragma unroll
    for (int phase = 0; phase < 2; phase++) {
        const float* W = phase ? Wv : Wk;
        float* outp = (phase ? g_v : g_k) + (size_t)b * CH * NN + n0;

        float acc[4][8][4];
#pragma unroll
        for (int mf = 0; mf < 4; mf++)
#pragma unroll
            for (int nf = 0; nf < 8; nf++)
#pragma unroll
                for (int i = 0; i < 4; i++) acc[mf][nf][i] = 0.f;

        float4 pw[8];
        // prefetch chunk 0
#pragma unroll
        for (int it = 0; it < 8; it++)
            pw[it] = *reinterpret_cast<const float4*>(&W[(wr + it * 32) * CH + wc4]);
#pragma unroll
        for (int it = 0; it < 8; it++) {
            union { __nv_bfloat162 h[2]; uint2 u; } cv;
            cv.h[0] = __floats2bfloat162_rn(pw[it].x, pw[it].y);
            cv.h[1] = __floats2bfloat162_rn(pw[it].z, pw[it].w);
            *reinterpret_cast<uint2*>(smem + SM_W0 + (wr + it * 32) * WPITCH + wc4 * 2) = cv.u;
        }
        __syncthreads();

        for (int kc = 0; kc < 8; kc++) {
            if (kc < 7) {
#pragma unroll
                for (int it = 0; it < 8; it++)
                    pw[it] = *reinterpret_cast<const float4*>(
                        &W[(wr + it * 32) * CH + (kc + 1) * 32 + wc4]);
            }
            const uint32_t abase = sb + ((kc & 1) ? SM_W1 : SM_W0) + aoff;
#pragma unroll
            for (int k16 = 0; k16 < 2; k16++) {
                const uint32_t bbase = addrB0 + (uint32_t)((kc * 32 + k16 * 16) * XPITCH);
                uint32_t bf[4][4];
#pragma unroll
                for (int p = 0; p < 4; p++)
                    LDSM_X4T(bf[p], bbase + p * 32);
#pragma unroll
                for (int mf = 0; mf < 4; mf++) {
                    uint32_t a[4];
                    LDSM_X4(a, abase + mf * 16 * WPITCH + k16 * 32);
#pragma unroll
                    for (int p = 0; p < 4; p++) {
                        MMA16816(acc[mf][2 * p],     a, bf[p][0], bf[p][1]);
                        MMA16816(acc[mf][2 * p + 1], a, bf[p][2], bf[p][3]);
                    }
                }
            }
            if (kc < 7) {
                const int dst = ((kc + 1) & 1) ? SM_W1 : SM_W0;
#pragma unroll
                for (int it = 0; it < 8; it++) {
                    union { __nv_bfloat162 h[2]; uint2 u; } cv;
                    cv.h[0] = __floats2bfloat162_rn(pw[it].x, pw[it].y);
                    cv.h[1] = __floats2bfloat162_rn(pw[it].z, pw[it].w);
                    *reinterpret_cast<uint2*>(smem + dst + (wr + it * 32) * WPITCH + wc4 * 2) = cv.u;
                }
            }
            __syncthreads();
        }

        // ---- epilogue: direct fp32 stores (32B sectors via 4-lane float2) ----
#pragma unroll
        for (int mf = 0; mf < 4; mf++) {
            const int m = wm + mf * 16 + (lane >> 2);
#pragma unroll
            for (int nf = 0; nf < 8; nf++) {
                const int n = wn + nf * 8 + (lane & 3) * 2;
                *reinterpret_cast<float2*>(&outp[(size_t)m * NN + n]) =
                    make_float2(acc[mf][nf][0], acc[mf][nf][1]);
                *reinterpret_cast<float2*>(&outp[(size_t)(m + 8) * NN + n]) =
                    make_float2(acc[mf][nf][2], acc[mf][nf][3]);
            }
        }
    }
}

// ================= Kernel 2: band scores -> softmax weights =================
__global__ __launch_bounds__(256) void score_kernel(const float* __restrict__ hidden) {
    const int b  = blockIdx.y;
    const int n0 = blockIdx.x * 64;
    const int tid = threadIdx.x;
    const int tx = tid & 63;
    const int ty = tid >> 6;
    const float* q  = hidden + (size_t)b * CH * NN;
    const float* kb = g_k    + (size_t)b * CH * NN;

    __shared__ float sk[8][72];
    __shared__ float red[4][5][64];

    float acc[5] = {0.f, 0.f, 0.f, 0.f, 0.f};

    for (int rb = 0; rb < CH; rb += 8) {
        __syncthreads();
        for (int i = tid; i < 8 * 68; i += 256) {
            int rr = i / 68;
            int j  = i - rr * 68;
            int ns = n0 - 2 + j;
            sk[rr][j] = ((unsigned)ns < (unsigned)NN)
                            ? kb[(size_t)(rb + rr) * NN + ns] : 0.f;
        }
        __syncthreads();
#pragma unroll
        for (int h = 0; h < 2; h++) {
            int rr = ty + h * 4;
            float qv = q[(size_t)(rb + rr) * NN + n0 + tx] * QSCALE;
#pragma unroll
            for (int d = 0; d < 5; d++) acc[d] += qv * sk[rr][tx + d];
        }
    }
    __syncthreads();
#pragma unroll
    for (int d = 0; d < 5; d++) red[ty][d][tx] = acc[d];
    __syncthreads();

    if (ty == 0) {
        int n = n0 + tx;
        float D = 0.f;
        float w[5];
        int nv = 0;
#pragma unroll
        for (int d = 0; d < 5; d++) {
            float s = red[0][d][tx] + red[1][d][tx] + red[2][d][tx] + red[3][d][tx];
            int m = n + d - 2;
            if ((unsigned)m < (unsigned)NN) {
                float e = expf(s);
                D += e;
                w[d] = e - 1.f;
                nv++;
            } else {
                w[d] = 0.f;
            }
        }
        D += (float)(NN - nv);
        float inv = 1.f / D;
        g_invD[b * NN + n] = inv;
#pragma unroll
        for (int d = 0; d < 5; d++)
            g_Wm[((size_t)b * 5 + d) * NN + n] = w[d] * inv;
    }
}

// ================= Kernel 3: g[b,c] = sum_n v[b,c,n]/D(n) =================
__global__ __launch_bounds__(256) void gsum_kernel() {
    const int b = blockIdx.y;
    const int c = blockIdx.x;
    const float4* v4 = reinterpret_cast<const float4*>(g_v + ((size_t)b * CH + c) * NN);
    const float4* d4 = reinterpret_cast<const float4*>(g_invD + b * NN);
    float s = 0.f;
#pragma unroll
    for (int i = threadIdx.x; i < NN / 4; i += 256) {
        float4 a = v4[i], d = d4[i];
        s += a.x * d.x + a.y * d.y + a.z * d.z + a.w * d.w;
    }
#pragma unroll
    for (int k = 16; k > 0; k >>= 1)
        s += __shfl_xor_sync(0xFFFFFFFFu, s, k);
    __shared__ float sr[8];
    if ((threadIdx.x & 31) == 0) sr[threadIdx.x >> 5] = s;
    __syncthreads();
    if (threadIdx.x == 0) {
        float t = 0.f;
#pragma unroll
        for (int i = 0; i < 8; i++) t += sr[i];
        g_gc[b * CH + c] = t;
    }
}

// ================= Kernel 4: epilogue =================
__global__ __launch_bounds__(256) void out_kernel(const float* __restrict__ inp,
                                                  float* __restrict__ out) {
    const int b  = blockIdx.z;
    const int c  = blockIdx.y;
    const int m0 = blockIdx.x * 1024;
    const int tid = threadIdx.x;
    const float* v = g_v + ((size_t)b * CH + c) * NN;

    __shared__ float sv[1028];
    for (int i = tid; i < 1028; i += 256) {
        int ns = m0 - 2 + i;
        sv[i] = ((unsigned)ns < (unsigned)NN) ? v[ns] : 0.f;
    }
    __syncthreads();

    const float gval = g_gc[b * CH + c];
#pragma unroll
    for (int it = 0; it < 4; it++) {
        const int li = it * 256 + tid;
        const int m  = m0 + li;
        const size_t idx = ((size_t)b * CH + c) * NN + m;
        float acc = inp[idx] + gval;
#pragma unroll
        for (int o = -2; o <= 2; o++) {
            int n = m + o;
            if ((unsigned)n < (unsigned)NN)
                acc += sv[li + 2 + o] * g_Wm[((size_t)b * 5 + (2 - o)) * NN + n];
        }
        out[idx] = acc;
    }
}

// ================= launch =================
extern "C" void kernel_launch(void* const* d_in, const int* in_sizes, int n_in,
                              void* d_out, int out_size) {
    const float* inp    = (const float*)d_in[0];
    const float* hidden = (const float*)d_in[1];
    const float* Wk     = (const float*)d_in[2];
    const float* Wv     = (const float*)d_in[3];
    float* out = (float*)d_out;

    cudaFuncSetAttribute(kv_mma_kernel,
                         cudaFuncAttributeMaxDynamicSharedMemorySize, SM_TOT);
    kv_mma_kernel<<<dim3(NN / 128, NB), 256, SM_TOT>>>(inp, Wk, Wv);
    score_kernel<<<dim3(NN / 64, NB), 256>>>(hidden);
    gsum_kernel<<<dim3(CH, NB), 256>>>();
    out_kernel<<<dim3(NN / 1024, CH, NB), 256>>>(inp, out);
}

// round 12
// speedup vs baseline: 3.1031x; 1.3830x over previous
#include <cuda_runtime.h>
#include <cuda_bf16.h>
#include <cstdint>

#define NB 4
#define CH 256
#define NN 4096
#define QSCALE 0.0625f   // 1/sqrt(256)

// ---------------- scratch (static __device__, no allocation) ----------------
__device__ float g_k[NB * CH * NN];        // 16 MB
__device__ float g_v[NB * CH * NN];        // 16 MB
__device__ float g_invD[NB * NN];
__device__ float g_Wm[NB * 5 * NN];        // band weights: [b][d][n], d: m = n + d - 2
__device__ float g_gc[NB * CH];            // rank-1 term per (b, c)

// ================= portable PTX helpers (sm_80-level only) =================
__device__ __forceinline__ uint32_t s2u(const void* p) {
    uint32_t a;
    asm("{ .reg .u64 t; cvta.to.shared.u64 t, %1; cvt.u32.u64 %0, t; }"
        : "=r"(a) : "l"(p));
    return a;
}

#define LDSM_X4(R, addr) \
    asm volatile("ldmatrix.sync.aligned.m8n8.x4.shared.b16 {%0,%1,%2,%3}, [%4];" \
        : "=r"((R)[0]), "=r"((R)[1]), "=r"((R)[2]), "=r"((R)[3]) : "r"(addr))

#define LDSM_X4T(R, addr) \
    asm volatile("ldmatrix.sync.aligned.m8n8.x4.trans.shared.b16 {%0,%1,%2,%3}, [%4];" \
        : "=r"((R)[0]), "=r"((R)[1]), "=r"((R)[2]), "=r"((R)[3]) : "r"(addr))

#define MMA16816(D, A, B0, B1) \
    asm volatile("mma.sync.aligned.m16n8k16.row.col.f32.bf16.bf16.f32 " \
        "{%0,%1,%2,%3}, {%4,%5,%6,%7}, {%8,%9}, {%0,%1,%2,%3};" \
        : "+f"((D)[0]), "+f"((D)[1]), "+f"((D)[2]), "+f"((D)[3]) \
        : "r"((A)[0]), "r"((A)[1]), "r"((A)[2]), "r"((A)[3]), "r"(B0), "r"(B1))

// ================= Kernel 1: HMMA bf16 fused k/v GEMM (unchanged) =================
#define XPITCH 272
#define WPITCH 80
#define SM_X   0
#define SM_W0  69632                 // 256*272
#define SM_W1  90112                 // SM_W0 + 256*80
#define SM_TOT 110592                // SM_W1 + 256*80

__global__ __launch_bounds__(256) void kv_mma_kernel(const float* __restrict__ inp,
                                                     const float* __restrict__ Wk,
                                                     const float* __restrict__ Wv) {
    extern __shared__ char smem[];
    const uint32_t sb = s2u(smem);
    const int tid = threadIdx.x;
    const int wid = tid >> 5;
    const int lane = tid & 31;
    const int b = blockIdx.y;
    const int n0 = blockIdx.x * 128;
    const float* X = inp + (size_t)b * CH * NN;

    // ---- load X resident tile: fp32 -> bf16, rows pitch 272B ----
    {
        const int nn4 = (tid & 31) * 4;
#pragma unroll 8
        for (int it = 0; it < 32; it++) {
            int c = (tid >> 5) + it * 8;
            float4 x = *reinterpret_cast<const float4*>(&X[(size_t)c * NN + n0 + nn4]);
            union { __nv_bfloat162 h[2]; uint2 u; } cv;
            cv.h[0] = __floats2bfloat162_rn(x.x, x.y);
            cv.h[1] = __floats2bfloat162_rn(x.z, x.w);
            *reinterpret_cast<uint2*>(smem + SM_X + c * XPITCH + nn4 * 2) = cv.u;
        }
    }

    const int wm = (wid >> 1) * 64;
    const int wn = (wid & 1) * 64;
    const uint32_t aoff = (uint32_t)((wm + (lane & 15)) * WPITCH + ((lane & 16) ? 16 : 0));
    const uint32_t addrB0 = sb + SM_X + (uint32_t)((lane & 15) * XPITCH +
                                                   (wn + ((lane & 16) ? 8 : 0)) * 2);

    const int wr = tid >> 3;
    const int wc4 = (tid & 7) * 4;

#pragma unroll
    for (int phase = 0; phase < 2; phase++) {
        const float* W = phase ? Wv : Wk;
        float* outp = (phase ? g_v : g_k) + (size_t)b * CH * NN + n0;

        float acc[4][8][4];
#pragma unroll
        for (int mf = 0; mf < 4; mf++)
#pragma unroll
            for (int nf = 0; nf < 8; nf++)
#pragma unroll
                for (int i = 0; i < 4; i++) acc[mf][nf][i] = 0.f;

        float4 pw[8];
#pragma unroll
        for (int it = 0; it < 8; it++)
            pw[it] = *reinterpret_cast<const float4*>(&W[(wr + it * 32) * CH + wc4]);
#pragma unroll
        for (int it = 0; it < 8; it++) {
            union { __nv_bfloat162 h[2]; uint2 u; } cv;
            cv.h[0] = __floats2bfloat162_rn(pw[it].x, pw[it].y);
            cv.h[1] = __floats2bfloat162_rn(pw[it].z, pw[it].w);
            *reinterpret_cast<uint2*>(smem + SM_W0 + (wr + it * 32) * WPITCH + wc4 * 2) = cv.u;
        }
        __syncthreads();

        for (int kc = 0; kc < 8; kc++) {
            if (kc < 7) {
#pragma unroll
                for (int it = 0; it < 8; it++)
                    pw[it] = *reinterpret_cast<const float4*>(
                        &W[(wr + it * 32) * CH + (kc + 1) * 32 + wc4]);
            }
            const uint32_t abase = sb + ((kc & 1) ? SM_W1 : SM_W0) + aoff;
#pragma unroll
            for (int k16 = 0; k16 < 2; k16++) {
                const uint32_t bbase = addrB0 + (uint32_t)((kc * 32 + k16 * 16) * XPITCH);
                uint32_t bf[4][4];
#pragma unroll
                for (int p = 0; p < 4; p++)
                    LDSM_X4T(bf[p], bbase + p * 32);
#pragma unroll
                for (int mf = 0; mf < 4; mf++) {
                    uint32_t a[4];
                    LDSM_X4(a, abase + mf * 16 * WPITCH + k16 * 32);
#pragma unroll
                    for (int p = 0; p < 4; p++) {
                        MMA16816(acc[mf][2 * p],     a, bf[p][0], bf[p][1]);
                        MMA16816(acc[mf][2 * p + 1], a, bf[p][2], bf[p][3]);
                    }
                }
            }
            if (kc < 7) {
                const int dst = ((kc + 1) & 1) ? SM_W1 : SM_W0;
#pragma unroll
                for (int it = 0; it < 8; it++) {
                    union { __nv_bfloat162 h[2]; uint2 u; } cv;
                    cv.h[0] = __floats2bfloat162_rn(pw[it].x, pw[it].y);
                    cv.h[1] = __floats2bfloat162_rn(pw[it].z, pw[it].w);
                    *reinterpret_cast<uint2*>(smem + dst + (wr + it * 32) * WPITCH + wc4 * 2) = cv.u;
                }
            }
            __syncthreads();
        }

#pragma unroll
        for (int mf = 0; mf < 4; mf++) {
            const int m = wm + mf * 16 + (lane >> 2);
#pragma unroll
            for (int nf = 0; nf < 8; nf++) {
                const int n = wn + nf * 8 + (lane & 3) * 2;
                *reinterpret_cast<float2*>(&outp[(size_t)m * NN + n]) =
                    make_float2(acc[mf][nf][0], acc[mf][nf][1]);
                *reinterpret_cast<float2*>(&outp[(size_t)(m + 8) * NN + n]) =
                    make_float2(acc[mf][nf][2], acc[mf][nf][3]);
            }
        }
    }
}

// ================= Kernel 2: band scores (sync-free streaming) =================
// block = (ntile of 128, b), 256 threads: tid&127 -> n, tid>>7 -> r half.
__global__ __launch_bounds__(256) void score_kernel(const float* __restrict__ hidden) {
    const int b  = blockIdx.y;
    const int n0 = blockIdx.x * 128;
    const int tid = threadIdx.x;
    const int nl = tid & 127;
    const int half = tid >> 7;
    const int n = n0 + nl;
    const float* q  = hidden + ((size_t)b * CH + half * 128) * NN + n;
    const float* kb = g_k    + ((size_t)b * CH + half * 128) * NN;

    // clamped band indices (weights for OOB m are zeroed in finalize)
    int ki[5];
#pragma unroll
    for (int d = 0; d < 5; d++) {
        int m = n + d - 2;
        ki[d] = m < 0 ? 0 : (m >= NN ? NN - 1 : m);
    }

    float acc[5] = {0.f, 0.f, 0.f, 0.f, 0.f};
#pragma unroll 4
    for (int r = 0; r < 128; r++) {
        const float qv = q[(size_t)r * NN];
        const float* kr = kb + (size_t)r * NN;
#pragma unroll
        for (int d = 0; d < 5; d++) acc[d] += qv * kr[ki[d]];
    }

    __shared__ float sacc[2][5][128];
#pragma unroll
    for (int d = 0; d < 5; d++) sacc[half][d][nl] = acc[d];
    __syncthreads();

    if (half == 0) {
        float D = 0.f;
        float w[5];
        int nv = 0;
#pragma unroll
        for (int d = 0; d < 5; d++) {
            float s = (sacc[0][d][nl] + sacc[1][d][nl]) * QSCALE;
            int m = n + d - 2;
            if ((unsigned)m < (unsigned)NN) {
                float e = expf(s);
                D += e;
                w[d] = e - 1.f;
                nv++;
            } else {
                w[d] = 0.f;
            }
        }
        D += (float)(NN - nv);
        float inv = 1.f / D;
        g_invD[b * NN + n] = inv;
#pragma unroll
        for (int d = 0; d < 5; d++)
            g_Wm[((size_t)b * 5 + d) * NN + n] = w[d] * inv;
    }
}

// ================= Kernel 3: g[b,c] = sum_n v[b,c,n]/D(n) =================
__global__ __launch_bounds__(256) void gsum_kernel() {
    const int b = blockIdx.y;
    const int c = blockIdx.x;
    const float4* v4 = reinterpret_cast<const float4*>(g_v + ((size_t)b * CH + c) * NN);
    const float4* d4 = reinterpret_cast<const float4*>(g_invD + b * NN);
    float s = 0.f;
#pragma unroll
    for (int i = threadIdx.x; i < NN / 4; i += 256) {
        float4 a = v4[i], d = d4[i];
        s += a.x * d.x + a.y * d.y + a.z * d.z + a.w * d.w;
    }
#pragma unroll
    for (int k = 16; k > 0; k >>= 1)
        s += __shfl_xor_sync(0xFFFFFFFFu, s, k);
    __shared__ float sr[8];
    if ((threadIdx.x & 31) == 0) sr[threadIdx.x >> 5] = s;
    __syncthreads();
    if (threadIdx.x == 0) {
        float t = 0.f;
#pragma unroll
        for (int i = 0; i < 8; i++) t += sr[i];
        g_gc[b * CH + c] = t;
    }
}

// ================= Kernel 4: epilogue (register-cached band weights) =======
// block = (mtile of 1024, cgroup of 16, b); thread owns 4 contiguous m,
// caches its 20 band weights in registers, loops 16 channels streaming.
#define CG 16
__global__ __launch_bounds__(256) void out_kernel(const float* __restrict__ inp,
                                                  float* __restrict__ out) {
    const int b  = blockIdx.z;
    const int c0 = blockIdx.y * CG;
    const int m0 = blockIdx.x * 1024 + threadIdx.x * 4;   // this thread's 4 m's

    // ---- load 20 band weights once: w[o+2][j] = Wm[2-o][m0+j+o] (0 if OOB) ----
    float w[5][4];
#pragma unroll
    for (int o = -2; o <= 2; o++) {
        const float* Wrow = g_Wm + ((size_t)b * 5 + (2 - o)) * NN;
#pragma unroll
        for (int j = 0; j < 4; j++) {
            int nidx = m0 + j + o;
            w[o + 2][j] = ((unsigned)nidx < (unsigned)NN) ? Wrow[nidx] : 0.f;
        }
    }
    const int vL2 = max(m0 - 2, 0), vL1 = max(m0 - 1, 0);
    const int vR1 = min(m0 + 4, NN - 1), vR2 = min(m0 + 5, NN - 1);

    const float* gcb = g_gc + b * CH + c0;

#pragma unroll 2
    for (int ci = 0; ci < CG; ci++) {
        const size_t rowoff = ((size_t)b * CH + c0 + ci) * NN;
        const float* v = g_v + rowoff;
        const float gval = gcb[ci];

        // v window: vwin[0..7] = v[m0-2 .. m0+5] (clamped; OOB masked by zero w)
        float4 vm = *reinterpret_cast<const float4*>(&v[m0]);
        float vwin[8];
        vwin[0] = v[vL2]; vwin[1] = v[vL1];
        vwin[2] = vm.x; vwin[3] = vm.y; vwin[4] = vm.z; vwin[5] = vm.w;
        vwin[6] = v[vR1]; vwin[7] = v[vR2];

        float4 xi = *reinterpret_cast<const float4*>(&inp[rowoff + m0]);
        float r[4] = { xi.x + gval, xi.y + gval, xi.z + gval, xi.w + gval };
#pragma unroll
        for (int j = 0; j < 4; j++)
#pragma unroll
            for (int oo = 0; oo < 5; oo++)
                r[j] += vwin[j + oo] * w[oo][j];

        *reinterpret_cast<float4*>(&out[rowoff + m0]) =
            make_float4(r[0], r[1], r[2], r[3]);
    }
}

// ================= launch =================
extern "C" void kernel_launch(void* const* d_in, const int* in_sizes, int n_in,
                              void* d_out, int out_size) {
    const float* inp    = (const float*)d_in[0];
    const float* hidden = (const float*)d_in[1];
    const float* Wk     = (const float*)d_in[2];
    const float* Wv     = (const float*)d_in[3];
    float* out = (float*)d_out;

    cudaFuncSetAttribute(kv_mma_kernel,
                         cudaFuncAttributeMaxDynamicSharedMemorySize, SM_TOT);
    kv_mma_kernel<<<dim3(NN / 128, NB), 256, SM_TOT>>>(inp, Wk, Wv);
    score_kernel<<<dim3(NN / 128, NB), 256>>>(hidden);
    gsum_kernel<<<dim3(CH, NB), 256>>>();
    out_kernel<<<dim3(NN / 1024, CH / CG, NB), 256>>>(inp, out);
}

// round 15
// speedup vs baseline: 3.3536x; 1.0807x over previous
#include <cuda_runtime.h>
#include <cuda_bf16.h>
#include <cstdint>

#define NB 4
#define CH 256
#define NN 4096
#define QSCALE 0.0625f   // 1/sqrt(256)

// ---------------- scratch (static __device__, no allocation) ----------------
__device__ float g_k[NB * CH * NN];        // 16 MB
__device__ float g_v[NB * CH * NN];        // 16 MB
__device__ float g_invD[NB * NN];
__device__ float g_Wm[NB * 5 * NN];        // band weights: [b][d][n], d: m = n + d - 2
__device__ float g_gc[NB * CH];            // rank-1 term per (b, c)

// ================= portable PTX helpers (sm_80-level only) =================
__device__ __forceinline__ uint32_t s2u(const void* p) {
    uint32_t a;
    asm("{ .reg .u64 t; cvta.to.shared.u64 t, %1; cvt.u32.u64 %0, t; }"
        : "=r"(a) : "l"(p));
    return a;
}

#define LDSM_X4(R, addr) \
    asm volatile("ldmatrix.sync.aligned.m8n8.x4.shared.b16 {%0,%1,%2,%3}, [%4];" \
        : "=r"((R)[0]), "=r"((R)[1]), "=r"((R)[2]), "=r"((R)[3]) : "r"(addr))

#define LDSM_X4T(R, addr) \
    asm volatile("ldmatrix.sync.aligned.m8n8.x4.trans.shared.b16 {%0,%1,%2,%3}, [%4];" \
        : "=r"((R)[0]), "=r"((R)[1]), "=r"((R)[2]), "=r"((R)[3]) : "r"(addr))

#define MMA16816(D, A, B0, B1) \
    asm volatile("mma.sync.aligned.m16n8k16.row.col.f32.bf16.bf16.f32 " \
        "{%0,%1,%2,%3}, {%4,%5,%6,%7}, {%8,%9}, {%0,%1,%2,%3};" \
        : "+f"((D)[0]), "+f"((D)[1]), "+f"((D)[2]), "+f"((D)[3]) \
        : "r"((A)[0]), "r"((A)[1]), "r"((A)[2]), "r"((A)[3]), "r"(B0), "r"(B1))

// ================= Kernel 1: HMMA bf16 fused k/v GEMM (512 threads) ========
// Per CTA: batch b, 128 n-cols, 256 m rows, K = 256.
//   X resident: 256(c) x 128(n) bf16, pitch 272B.  W streamed: k-chunks of 32,
//   256(m) x 32(k) bf16 pitch 80B, double buffered.
// 16 warps: grid 4(m) x 4(n); warp tile 64m x 32n; m16n8k16, fp32 accum.
#define XPITCH 272
#define WPITCH 80
#define SM_X   0
#define SM_W0  69632                 // 256*272
#define SM_W1  90112                 // SM_W0 + 256*80
#define SM_TOT 110592                // SM_W1 + 256*80

__global__ __launch_bounds__(512, 1) void kv_mma_kernel(const float* __restrict__ inp,
                                                        const float* __restrict__ Wk,
                                                        const float* __restrict__ Wv) {
    extern __shared__ char smem[];
    const uint32_t sb = s2u(smem);
    const int tid = threadIdx.x;
    const int wid = tid >> 5;
    const int lane = tid & 31;
    const int b = blockIdx.y;
    const int n0 = blockIdx.x * 128;
    const float* X = inp + (size_t)b * CH * NN;

    // ---- load X resident tile: fp32 -> bf16, rows pitch 272B ----
    {
        const int nn4 = (tid & 31) * 4;
        const int c0 = tid >> 5;
#pragma unroll 8
        for (int it = 0; it < 16; it++) {
            int c = c0 + it * 16;
            float4 x = *reinterpret_cast<const float4*>(&X[(size_t)c * NN + n0 + nn4]);
            union { __nv_bfloat162 h[2]; uint2 u; } cv;
            cv.h[0] = __floats2bfloat162_rn(x.x, x.y);
            cv.h[1] = __floats2bfloat162_rn(x.z, x.w);
            *reinterpret_cast<uint2*>(smem + SM_X + c * XPITCH + nn4 * 2) = cv.u;
        }
    }

    const int wm = (wid >> 2) * 64;       // 4 m-groups
    const int wn = (wid & 3) * 32;        // 4 n-groups
    const uint32_t aoff = (uint32_t)((wm + (lane & 15)) * WPITCH + ((lane & 16) ? 16 : 0));
    const uint32_t addrB0 = sb + SM_X + (uint32_t)((lane & 15) * XPITCH +
                                                   (wn + ((lane & 16) ? 8 : 0)) * 2);

    const int wr0 = tid >> 3;             // W loader: row base (stride 64), 4 rows/thread
    const int wc4 = (tid & 7) * 4;        // 4-col group within 32-k chunk

#pragma unroll
    for (int phase = 0; phase < 2; phase++) {
        const float* W = phase ? Wv : Wk;
        float* outp = (phase ? g_v : g_k) + (size_t)b * CH * NN + n0;

        float acc[4][4][4];
#pragma unroll
        for (int mf = 0; mf < 4; mf++)
#pragma unroll
            for (int nf = 0; nf < 4; nf++)
#pragma unroll
                for (int i = 0; i < 4; i++) acc[mf][nf][i] = 0.f;

        float4 pw[4];
#pragma unroll
        for (int it = 0; it < 4; it++)
            pw[it] = *reinterpret_cast<const float4*>(&W[(wr0 + it * 64) * CH + wc4]);
#pragma unroll
        for (int it = 0; it < 4; it++) {
            union { __nv_bfloat162 h[2]; uint2 u; } cv;
            cv.h[0] = __floats2bfloat162_rn(pw[it].x, pw[it].y);
            cv.h[1] = __floats2bfloat162_rn(pw[it].z, pw[it].w);
            *reinterpret_cast<uint2*>(smem + SM_W0 + (wr0 + it * 64) * WPITCH + wc4 * 2) = cv.u;
        }
        __syncthreads();

        for (int kc = 0; kc < 8; kc++) {
            if (kc < 7) {
#pragma unroll
                for (int it = 0; it < 4; it++)
                    pw[it] = *reinterpret_cast<const float4*>(
                        &W[(wr0 + it * 64) * CH + (kc + 1) * 32 + wc4]);
            }
            const uint32_t abase = sb + ((kc & 1) ? SM_W1 : SM_W0) + aoff;
#pragma unroll
            for (int k16 = 0; k16 < 2; k16++) {
                const uint32_t bbase = addrB0 + (uint32_t)((kc * 32 + k16 * 16) * XPITCH);
                uint32_t bf[2][4];
#pragma unroll
                for (int p = 0; p < 2; p++)
                    LDSM_X4T(bf[p], bbase + p * 32);
#pragma unroll
                for (int mf = 0; mf < 4; mf++) {
                    uint32_t a[4];
                    LDSM_X4(a, abase + mf * 16 * WPITCH + k16 * 32);
#pragma unroll
                    for (int p = 0; p < 2; p++) {
                        MMA16816(acc[mf][2 * p],     a, bf[p][0], bf[p][1]);
                        MMA16816(acc[mf][2 * p + 1], a, bf[p][2], bf[p][3]);
                    }
                }
            }
            if (kc < 7) {
                const int dst = ((kc + 1) & 1) ? SM_W1 : SM_W0;
#pragma unroll
                for (int it = 0; it < 4; it++) {
                    union { __nv_bfloat162 h[2]; uint2 u; } cv;
                    cv.h[0] = __floats2bfloat162_rn(pw[it].x, pw[it].y);
                    cv.h[1] = __floats2bfloat162_rn(pw[it].z, pw[it].w);
                    *reinterpret_cast<uint2*>(smem + dst + (wr0 + it * 64) * WPITCH + wc4 * 2) = cv.u;
                }
            }
            __syncthreads();
        }

        // ---- direct fp32 stores ----
#pragma unroll
        for (int mf = 0; mf < 4; mf++) {
            const int m = wm + mf * 16 + (lane >> 2);
#pragma unroll
            for (int nf = 0; nf < 4; nf++) {
                const int n = wn + nf * 8 + (lane & 3) * 2;
                *reinterpret_cast<float2*>(&outp[(size_t)m * NN + n]) =
                    make_float2(acc[mf][nf][0], acc[mf][nf][1]);
                *reinterpret_cast<float2*>(&outp[(size_t)(m + 8) * NN + n]) =
                    make_float2(acc[mf][nf][2], acc[mf][nf][3]);
            }
        }
    }
}

// ================= Kernel 2: band scores (sync-free streaming) =================
__global__ __launch_bounds__(256) void score_kernel(const float* __restrict__ hidden) {
    const int b  = blockIdx.y;
    const int n0 = blockIdx.x * 128;
    const int tid = threadIdx.x;
    const int nl = tid & 127;
    const int half = tid >> 7;
    const int n = n0 + nl;
    const float* q  = hidden + ((size_t)b * CH + half * 128) * NN + n;
    const float* kb = g_k    + ((size_t)b * CH + half * 128) * NN;

    int ki[5];
#pragma unroll
    for (int d = 0; d < 5; d++) {
        int m = n + d - 2;
        ki[d] = m < 0 ? 0 : (m >= NN ? NN - 1 : m);
    }

    float acc[5] = {0.f, 0.f, 0.f, 0.f, 0.f};
#pragma unroll 4
    for (int r = 0; r < 128; r++) {
        const float qv = q[(size_t)r * NN];
        const float* kr = kb + (size_t)r * NN;
#pragma unroll
        for (int d = 0; d < 5; d++) acc[d] += qv * kr[ki[d]];
    }

    __shared__ float sacc[2][5][128];
#pragma unroll
    for (int d = 0; d < 5; d++) sacc[half][d][nl] = acc[d];
    __syncthreads();

    if (half == 0) {
        float D = 0.f;
        float w[5];
        int nv = 0;
#pragma unroll
        for (int d = 0; d < 5; d++) {
            float s = (sacc[0][d][nl] + sacc[1][d][nl]) * QSCALE;
            int m = n + d - 2;
            if ((unsigned)m < (unsigned)NN) {
                float e = expf(s);
                D += e;
                w[d] = e - 1.f;
                nv++;
            } else {
                w[d] = 0.f;
            }
        }
        D += (float)(NN - nv);
        float inv = 1.f / D;
        g_invD[b * NN + n] = inv;
#pragma unroll
        for (int d = 0; d < 5; d++)
            g_Wm[((size_t)b * 5 + d) * NN + n] = w[d] * inv;
    }
}

// ================= Kernel 3: g[b,c] = sum_n v[b,c,n]/D(n) =================
__global__ __launch_bounds__(256) void gsum_kernel() {
    const int b = blockIdx.y;
    const int c = blockIdx.x;
    const float4* v4 = reinterpret_cast<const float4*>(g_v + ((size_t)b * CH + c) * NN);
    const float4* d4 = reinterpret_cast<const float4*>(g_invD + b * NN);
    float s = 0.f;
#pragma unroll
    for (int i = threadIdx.x; i < NN / 4; i += 256) {
        float4 a = v4[i], d = d4[i];
        s += a.x * d.x + a.y * d.y + a.z * d.z + a.w * d.w;
    }
#pragma unroll
    for (int k = 16; k > 0; k >>= 1)
        s += __shfl_xor_sync(0xFFFFFFFFu, s, k);
    __shared__ float sr[8];
    if ((threadIdx.x & 31) == 0) sr[threadIdx.x >> 5] = s;
    __syncthreads();
    if (threadIdx.x == 0) {
        float t = 0.f;
#pragma unroll
        for (int i = 0; i < 8; i++) t += sr[i];
        g_gc[b * CH + c] = t;
    }
}

// ================= Kernel 4: epilogue (register-cached band weights) =======
#define CG 4
__global__ __launch_bounds__(256) void out_kernel(const float* __restrict__ inp,
                                                  float* __restrict__ out) {
    const int b  = blockIdx.z;
    const int c0 = blockIdx.y * CG;
    const int m0 = blockIdx.x * 1024 + threadIdx.x * 4;

    float w[5][4];
#pragma unroll
    for (int o = -2; o <= 2; o++) {
        const float* Wrow = g_Wm + ((size_t)b * 5 + (2 - o)) * NN;
#pragma unroll
        for (int j = 0; j < 4; j++) {
            int nidx = m0 + j + o;
            w[o + 2][j] = ((unsigned)nidx < (unsigned)NN) ? Wrow[nidx] : 0.f;
        }
    }
    const int vL2 = max(m0 - 2, 0), vL1 = max(m0 - 1, 0);
    const int vR1 = min(m0 + 4, NN - 1), vR2 = min(m0 + 5, NN - 1);

    const float* gcb = g_gc + b * CH + c0;

#pragma unroll
    for (int ci = 0; ci < CG; ci++) {
        const size_t rowoff = ((size_t)b * CH + c0 + ci) * NN;
        const float* v = g_v + rowoff;
        const float gval = gcb[ci];

        float4 vm = *reinterpret_cast<const float4*>(&v[m0]);
        float vwin[8];
        vwin[0] = v[vL2]; vwin[1] = v[vL1];
        vwin[2] = vm.x; vwin[3] = vm.y; vwin[4] = vm.z; vwin[5] = vm.w;
        vwin[6] = v[vR1]; vwin[7] = v[vR2];

        float4 xi = *reinterpret_cast<const float4*>(&inp[rowoff + m0]);
        float r[4] = { xi.x + gval, xi.y + gval, xi.z + gval, xi.w + gval };
#pragma unroll
        for (int j = 0; j < 4; j++)
#pragma unroll
            for (int oo = 0; oo < 5; oo++)
                r[j] += vwin[j + oo] * w[oo][j];

        *reinterpret_cast<float4*>(&out[rowoff + m0]) =
            make_float4(r[0], r[1], r[2], r[3]);
    }
}

// ================= launch =================
extern "C" void kernel_launch(void* const* d_in, const int* in_sizes, int n_in,
                              void* d_out, int out_size) {
    const float* inp    = (const float*)d_in[0];
    const float* hidden = (const float*)d_in[1];
    const float* Wk     = (const float*)d_in[2];
    const float* Wv     = (const float*)d_in[3];
    float* out = (float*)d_out;

    cudaFuncSetAttribute(kv_mma_kernel,
                         cudaFuncAttributeMaxDynamicSharedMemorySize, SM_TOT);
    kv_mma_kernel<<<dim3(NN / 128, NB), 512, SM_TOT>>>(inp, Wk, Wv);
    score_kernel<<<dim3(NN / 128, NB), 256>>>(hidden);
    gsum_kernel<<<dim3(CH, NB), 256>>>();
    out_kernel<<<dim3(NN / 1024, CH / CG, NB), 256>>>(inp, out);
}